// round 12
// baseline (speedup 1.0000x reference)
#include <cuda_runtime.h>
#include <cuda_fp16.h>

typedef unsigned int u32;

#define GN_EPS 1e-5f
// (1/sqrt(32)) * log2(e): softmax runs in base-2 domain
#define QSCALE 0.25501817097393111f

// ---------------- scratch (static device allocations, allowed) -------------
__device__ __align__(16) __half g_xh[4 * 128 * 4096];    // x in fp16 [b][c][n]
__device__ __align__(16) __half g_qh[4 * 4 * 4096 * 32]; // [b][h][n][d]
__device__ __align__(16) __half g_kh[4 * 4 * 4096 * 32];
__device__ __align__(16) __half g_vh[4 * 4 * 4096 * 32];
__device__ __align__(16) __half g_aoh[4 * 128 * 4096];   // attn out fp16 [b][c][n]
__device__ __align__(16) float g_y[4 * 128 * 4096];      // proj out fp32 [b][c][n]
__device__ float2 g_part[4 * 2 * 64 * 2];
__device__ float2 g_stats[16];

// ---------------- PTX helpers ----------------------------------------------
__device__ __forceinline__ float ex2(float x) {
    float r; asm("ex2.approx.ftz.f32 %0, %1;" : "=f"(r) : "f"(x)); return r;
}
__device__ __forceinline__ u32 ex2h2(u32 x) {
    u32 r; asm("ex2.approx.f16x2 %0, %1;" : "=r"(r) : "r"(x)); return r;
}
__device__ __forceinline__ void ldsm_x4(u32* r, u32 addr) {
    asm volatile("ldmatrix.sync.aligned.m8n8.x4.shared.b16 {%0,%1,%2,%3}, [%4];"
                 : "=r"(r[0]), "=r"(r[1]), "=r"(r[2]), "=r"(r[3]) : "r"(addr));
}
__device__ __forceinline__ void ldsm_x4_t(u32* r, u32 addr) {
    asm volatile("ldmatrix.sync.aligned.m8n8.x4.trans.shared.b16 {%0,%1,%2,%3}, [%4];"
                 : "=r"(r[0]), "=r"(r[1]), "=r"(r[2]), "=r"(r[3]) : "r"(addr));
}
__device__ __forceinline__ void mma16816(float* c, const u32* a, const u32* b) {
    asm volatile("mma.sync.aligned.m16n8k16.row.col.f32.f16.f16.f32 "
                 "{%0,%1,%2,%3}, {%4,%5,%6,%7}, {%8,%9}, {%0,%1,%2,%3};"
                 : "+f"(c[0]), "+f"(c[1]), "+f"(c[2]), "+f"(c[3])
                 : "r"(a[0]), "r"(a[1]), "r"(a[2]), "r"(a[3]), "r"(b[0]), "r"(b[1]));
}
__device__ __forceinline__ u32 packh2(float a, float b) {
    __half2 h = __floats2half2_rn(a, b);
    return *(u32*)&h;
}
__device__ __forceinline__ __half2 u2h(u32 x) { __half2 h; *(u32*)&h = x; return h; }
__device__ __forceinline__ void cp16(u32 smem, const void* gmem) {
    asm volatile("cp.async.cg.shared.global [%0], [%1], 16;" :: "r"(smem), "l"(gmem));
}

// ===========================================================================
// Kernel 0: convert x fp32 -> fp16
// ===========================================================================
__global__ __launch_bounds__(256) void cvt_kernel(const float* __restrict__ x) {
    const int i = blockIdx.x * 256 + threadIdx.x;  // 524288 float4s
    float4 v = *(const float4*)&x[i * 4];
    *(__half2*)&g_xh[i * 4 + 0] = __floats2half2_rn(v.x, v.y);
    *(__half2*)&g_xh[i * 4 + 2] = __floats2half2_rn(v.z, v.w);
}

// ===========================================================================
// Kernel 1: QKV projection on tensor cores.
// out[m,n] = sum_k W[m,k] * x[k,n].  Tile 64(m) x 64(n), k=128.
// grid (64, 6, 4), 128 threads (4 warps, 16 m-rows each).
// ===========================================================================
__global__ __launch_bounds__(128) void qkv_kernel(const float* __restrict__ w) {
    __shared__ __align__(16) char smemBuf[17408 + 18432];
    __half* Ws = (__half*)smemBuf;                 // [64][136]
    __half* Xs = (__half*)(smemBuf + 17408);       // [128][72]
    __half* Osh = (__half*)smemBuf;                // overlay after mainloop [64n][72]

    const int b = blockIdx.z;
    const int n0 = blockIdx.x * 64;
    const int m0 = blockIdx.y * 64;
    const int tid = threadIdx.x;
    const int wrp = tid >> 5, lane = tid & 31;

    // stage W (fp32 -> fp16), 64x128
    for (int idx = tid; idx < 64 * 32; idx += 128) {
        int row = idx >> 5, c4 = idx & 31;
        float4 wv = *(const float4*)&w[(m0 + row) * 128 + c4 * 4];
        *(__half2*)&Ws[row * 136 + c4 * 4 + 0] = __floats2half2_rn(wv.x, wv.y);
        *(__half2*)&Ws[row * 136 + c4 * 4 + 2] = __floats2half2_rn(wv.z, wv.w);
    }
    // stage X tile [k=128][n=64] fp16
    for (int idx = tid; idx < 128 * 8; idx += 128) {
        int row = idx >> 3, seg = idx & 7;
        *(uint4*)&Xs[row * 72 + seg * 8] =
            *(const uint4*)&g_xh[(b * 128 + row) * 4096 + n0 + seg * 8];
    }
    __syncthreads();

    float acc[8][4];
#pragma unroll
    for (int i = 0; i < 8; i++)
#pragma unroll
        for (int j = 0; j < 4; j++) acc[i][j] = 0.f;

    const u32 wsAddr = (u32)__cvta_generic_to_shared(
        &Ws[(wrp * 16 + (lane & 15)) * 136 + (lane >> 4) * 8]);
    const int vm = lane >> 3;
    const u32 xsAddr = (u32)__cvta_generic_to_shared(
        &Xs[((vm & 1) * 8 + (lane & 7)) * 72 + (vm >> 1) * 8]);

#pragma unroll
    for (int kk = 0; kk < 8; kk++) {
        u32 wa[4];
        ldsm_x4(wa, wsAddr + kk * 32);
#pragma unroll
        for (int np = 0; np < 4; np++) {
            u32 xb[4];
            ldsm_x4_t(xb, xsAddr + kk * 16 * 144 + np * 32);
            mma16816(acc[2 * np + 0], wa, xb + 0);
            mma16816(acc[2 * np + 1], wa, xb + 2);
        }
    }
    __syncthreads();   // done with Ws/Xs, reuse as Osh

    const float sc = (m0 < 128) ? QSCALE : 1.0f;
    const int g = lane >> 2, t4 = lane & 3;
#pragma unroll
    for (int nt = 0; nt < 8; nt++) {
        int col = nt * 8 + 2 * t4;
        int r0 = wrp * 16 + g;
        Osh[(col + 0) * 72 + r0 + 0] = __float2half(acc[nt][0] * sc);
        Osh[(col + 1) * 72 + r0 + 0] = __float2half(acc[nt][1] * sc);
        Osh[(col + 0) * 72 + r0 + 8] = __float2half(acc[nt][2] * sc);
        Osh[(col + 1) * 72 + r0 + 8] = __float2half(acc[nt][3] * sc);
    }
    __syncthreads();

    const int which = m0 >> 7;
    __half* dstbase = (which == 0) ? g_qh : ((which == 1) ? g_kh : g_vh);
    const int h0 = (m0 >> 5) & 3;
    const int n = tid >> 1, hi = tid & 1;
    __half* dst = &dstbase[((long)(b * 4 + h0 + hi) * 4096 + n0 + n) * 32];
    const __half* src = &Osh[n * 72 + hi * 32];
    *(uint4*)&dst[0]  = *(const uint4*)&src[0];
    *(uint4*)&dst[8]  = *(const uint4*)&src[8];
    *(uint4*)&dst[16] = *(const uint4*)&src[16];
    *(uint4*)&dst[24] = *(const uint4*)&src[24];
}

// ===========================================================================
// Kernel 2: fp16 tensor-core flash attention, cp.async double-buffered KV,
// f16x2 exp2.  grid (64, 4, 4), 128 threads.
// ===========================================================================
__global__ __launch_bounds__(128) void attn_kernel() {
    __shared__ __align__(16) __half Qs[64 * 40];
    __shared__ __align__(16) __half Ks[2][64 * 40];
    __shared__ __align__(16) __half Vs[2][64 * 40];
    __shared__ __align__(16) float Os[64 * 33];

    const int b = blockIdx.z, hh = blockIdx.y;
    const int q0 = blockIdx.x * 64;
    const int tid = threadIdx.x;
    const int wrp = tid >> 5, lane = tid & 31;
    const long bh = (long)(b * 4 + hh) * 4096;

    // stage Q tile
    {
        const uint4* qg = (const uint4*)&g_qh[(bh + q0) * 32];
        for (int i = tid; i < 256; i += 128) {
            int row = i >> 2, ch = i & 3;
            *(uint4*)&Qs[row * 40 + ch * 8] = qg[i];
        }
    }

    const uint4* kg = (const uint4*)&g_kh[bh * 32];
    const uint4* vg = (const uint4*)&g_vh[bh * 32];
    const u32 ksmem = (u32)__cvta_generic_to_shared(&Ks[0][0]);
    const u32 vsmem = (u32)__cvta_generic_to_shared(&Vs[0][0]);
    // per-thread cp.async slots: i = tid (rows 0-31), i+128 (rows 32-63)
    const u32 off0 = (tid >> 2) * 80 + (tid & 3) * 16;
    const u32 off1 = off0 + 32 * 80;

    // prologue: issue tile 0 into buf 0
    cp16(ksmem + off0, kg + tid);
    cp16(ksmem + off1, kg + tid + 128);
    cp16(vsmem + off0, vg + tid);
    cp16(vsmem + off1, vg + tid + 128);
    asm volatile("cp.async.commit_group;");

    __syncthreads();
    // Q A-fragments (held all kernel)
    u32 qa[8];
    {
        int r = lane & 15, cc = lane >> 4;
        u32 a = (u32)__cvta_generic_to_shared(&Qs[(wrp * 16 + r) * 40 + cc * 8]);
        ldsm_x4(qa + 0, a);
        ldsm_x4(qa + 4, a + 32);
    }

    float o[4][4];
#pragma unroll
    for (int i = 0; i < 4; i++)
#pragma unroll
        for (int j = 0; j < 4; j++) o[i][j] = 0.f;
    float m0 = -1e30f, m1 = -1e30f, l0 = 0.f, l1 = 0.f;

    const u32 kaddr = (u32)__cvta_generic_to_shared(
        &Ks[0][(lane & 7) * 40 + (lane >> 3) * 8]);
    const int vm = lane >> 3;
    const u32 vaddr = (u32)__cvta_generic_to_shared(
        &Vs[0][((vm & 1) * 8 + (lane & 7)) * 40 + (vm >> 1) * 8]);

    for (int t0 = 0; t0 < 4096; t0 += 64) {
        const int buf = (t0 >> 6) & 1;
        const u32 bo = buf * 5120;
        // prefetch next tile into other buffer
        if (t0 + 64 < 4096) {
            const uint4* ks = kg + (t0 + 64) * 4;
            const uint4* vs = vg + (t0 + 64) * 4;
            const u32 nb = (buf ^ 1) * 5120;
            cp16(ksmem + nb + off0, ks + tid);
            cp16(ksmem + nb + off1, ks + tid + 128);
            cp16(vsmem + nb + off0, vs + tid);
            cp16(vsmem + nb + off1, vs + tid + 128);
        }
        asm volatile("cp.async.commit_group;");
        asm volatile("cp.async.wait_group 1;");
        __syncthreads();

        // ---- S = Q K^T
        float s[8][4];
#pragma unroll
        for (int nt = 0; nt < 8; nt++) {
            s[nt][0] = s[nt][1] = s[nt][2] = s[nt][3] = 0.f;
            u32 kb[4];
            ldsm_x4(kb, kaddr + bo + nt * 640);
            mma16816(s[nt], qa + 0, kb + 0);
            mma16816(s[nt], qa + 4, kb + 2);
        }

        // ---- online softmax (base-2, f16x2 exp)
        float mx0 = -1e30f, mx1 = -1e30f;
#pragma unroll
        for (int nt = 0; nt < 8; nt++) {
            mx0 = fmaxf(mx0, fmaxf(s[nt][0], s[nt][1]));
            mx1 = fmaxf(mx1, fmaxf(s[nt][2], s[nt][3]));
        }
        mx0 = fmaxf(mx0, __shfl_xor_sync(0xffffffffu, mx0, 1));
        mx0 = fmaxf(mx0, __shfl_xor_sync(0xffffffffu, mx0, 2));
        mx1 = fmaxf(mx1, __shfl_xor_sync(0xffffffffu, mx1, 1));
        mx1 = fmaxf(mx1, __shfl_xor_sync(0xffffffffu, mx1, 2));
        float nm0 = fmaxf(m0, mx0), nm1 = fmaxf(m1, mx1);
        float corr0 = ex2(m0 - nm0), corr1 = ex2(m1 - nm1);
        m0 = nm0; m1 = nm1;

        u32 pa[8][2];
#pragma unroll
        for (int nt = 0; nt < 8; nt++) {
            pa[nt][0] = ex2h2(packh2(s[nt][0] - m0, s[nt][1] - m0));
            pa[nt][1] = ex2h2(packh2(s[nt][2] - m1, s[nt][3] - m1));
        }
        // l-sums via shallow half2 tree then fp32
        __half2 t00 = __hadd2(__hadd2(u2h(pa[0][0]), u2h(pa[1][0])),
                              __hadd2(u2h(pa[2][0]), u2h(pa[3][0])));
        __half2 t01 = __hadd2(__hadd2(u2h(pa[4][0]), u2h(pa[5][0])),
                              __hadd2(u2h(pa[6][0]), u2h(pa[7][0])));
        __half2 t10 = __hadd2(__hadd2(u2h(pa[0][1]), u2h(pa[1][1])),
                              __hadd2(u2h(pa[2][1]), u2h(pa[3][1])));
        __half2 t11 = __hadd2(__hadd2(u2h(pa[4][1]), u2h(pa[5][1])),
                              __hadd2(u2h(pa[6][1]), u2h(pa[7][1])));
        float2 f0 = __half22float2(__hadd2(t00, t01));
        float2 f1 = __half22float2(__hadd2(t10, t11));
        l0 = l0 * corr0 + f0.x + f0.y;
        l1 = l1 * corr1 + f1.x + f1.y;
#pragma unroll
        for (int nd = 0; nd < 4; nd++) {
            o[nd][0] *= corr0; o[nd][1] *= corr0;
            o[nd][2] *= corr1; o[nd][3] *= corr1;
        }

        // ---- O += P V
#pragma unroll
        for (int kv = 0; kv < 4; kv++) {
            u32 A[4] = {pa[2 * kv][0], pa[2 * kv][1],
                        pa[2 * kv + 1][0], pa[2 * kv + 1][1]};
#pragma unroll
            for (int dh = 0; dh < 2; dh++) {
                u32 vb[4];
                ldsm_x4_t(vb, vaddr + bo + kv * 1280 + dh * 32);
                mma16816(o[2 * dh + 0], A, vb + 0);
                mma16816(o[2 * dh + 1], A, vb + 2);
            }
        }
        __syncthreads();
    }

    // ---- epilogue
    l0 += __shfl_xor_sync(0xffffffffu, l0, 1);
    l0 += __shfl_xor_sync(0xffffffffu, l0, 2);
    l1 += __shfl_xor_sync(0xffffffffu, l1, 1);
    l1 += __shfl_xor_sync(0xffffffffu, l1, 2);
    const float inv0 = 1.f / l0, inv1 = 1.f / l1;
    const int grp = lane >> 2, t4 = lane & 3;
#pragma unroll
    for (int nd = 0; nd < 4; nd++) {
        Os[(wrp * 16 + grp) * 33 + nd * 8 + 2 * t4 + 0] = o[nd][0] * inv0;
        Os[(wrp * 16 + grp) * 33 + nd * 8 + 2 * t4 + 1] = o[nd][1] * inv0;
        Os[(wrp * 16 + grp + 8) * 33 + nd * 8 + 2 * t4 + 0] = o[nd][2] * inv1;
        Os[(wrp * 16 + grp + 8) * 33 + nd * 8 + 2 * t4 + 1] = o[nd][3] * inv1;
    }
    __syncthreads();

    __half* ob = &g_aoh[(long)(b * 128 + hh * 32) * 4096 + q0];
    const int dd = tid >> 2, seg = tid & 3;
    union { __half hx[16]; uint4 ux[2]; } tmp;
#pragma unroll
    for (int i = 0; i < 16; i++)
        tmp.hx[i] = __float2half(Os[(seg * 16 + i) * 33 + dd]);
    uint4* dsth = (uint4*)&ob[dd * 4096 + seg * 16];
    dsth[0] = tmp.ux[0];
    dsth[1] = tmp.ux[1];
}

// ===========================================================================
// Kernel 3: output projection on tensor cores + bias + GN partials.
// grid (64, 2, 4), 128 threads.
// ===========================================================================
__global__ __launch_bounds__(128) void proj_kernel(const float* __restrict__ w,
                                                   const float* __restrict__ bias) {
    __shared__ __align__(16) char smemBuf[17408 + 18432];
    __half* Ws = (__half*)smemBuf;              // [64][136]
    __half* Xs = (__half*)(smemBuf + 17408);    // [128][72]
    float* Osf = (float*)smemBuf;               // overlay [64m][68]
    __shared__ float wred[4][2];

    const int b = blockIdx.z;
    const int n0 = blockIdx.x * 64;
    const int m0 = blockIdx.y * 64;
    const int tid = threadIdx.x;
    const int wrp = tid >> 5, lane = tid & 31;

    for (int idx = tid; idx < 64 * 32; idx += 128) {
        int row = idx >> 5, c4 = idx & 31;
        float4 wv = *(const float4*)&w[(m0 + row) * 128 + c4 * 4];
        *(__half2*)&Ws[row * 136 + c4 * 4 + 0] = __floats2half2_rn(wv.x, wv.y);
        *(__half2*)&Ws[row * 136 + c4 * 4 + 2] = __floats2half2_rn(wv.z, wv.w);
    }
    for (int idx = tid; idx < 128 * 8; idx += 128) {
        int row = idx >> 3, seg = idx & 7;
        *(uint4*)&Xs[row * 72 + seg * 8] =
            *(const uint4*)&g_aoh[(long)(b * 128 + row) * 4096 + n0 + seg * 8];
    }
    __syncthreads();

    float acc[8][4];
#pragma unroll
    for (int i = 0; i < 8; i++)
#pragma unroll
        for (int j = 0; j < 4; j++) acc[i][j] = 0.f;

    const u32 wsAddr = (u32)__cvta_generic_to_shared(
        &Ws[(wrp * 16 + (lane & 15)) * 136 + (lane >> 4) * 8]);
    const int vm = lane >> 3;
    const u32 xsAddr = (u32)__cvta_generic_to_shared(
        &Xs[((vm & 1) * 8 + (lane & 7)) * 72 + (vm >> 1) * 8]);

#pragma unroll
    for (int kk = 0; kk < 8; kk++) {
        u32 wa[4];
        ldsm_x4(wa, wsAddr + kk * 32);
#pragma unroll
        for (int np = 0; np < 4; np++) {
            u32 xb[4];
            ldsm_x4_t(xb, xsAddr + kk * 16 * 144 + np * 32);
            mma16816(acc[2 * np + 0], wa, xb + 0);
            mma16816(acc[2 * np + 1], wa, xb + 2);
        }
    }
    __syncthreads();   // reuse smem as Osf

    const int g = lane >> 2, t4 = lane & 3;
    const int r0 = wrp * 16 + g;
    const float b0 = bias[m0 + r0], b1 = bias[m0 + r0 + 8];
    float lsum = 0.f, lsq = 0.f;
#pragma unroll
    for (int nt = 0; nt < 8; nt++) {
        int col = nt * 8 + 2 * t4;
        float v0 = acc[nt][0] + b0, v1 = acc[nt][1] + b0;
        float v2 = acc[nt][2] + b1, v3 = acc[nt][3] + b1;
        Osf[(r0 + 0) * 68 + col + 0] = v0;
        Osf[(r0 + 0) * 68 + col + 1] = v1;
        Osf[(r0 + 8) * 68 + col + 0] = v2;
        Osf[(r0 + 8) * 68 + col + 1] = v3;
        lsum += (v0 + v1) + (v2 + v3);
        lsq = fmaf(v0, v0, lsq); lsq = fmaf(v1, v1, lsq);
        lsq = fmaf(v2, v2, lsq); lsq = fmaf(v3, v3, lsq);
    }
#pragma unroll
    for (int off = 16; off > 0; off >>= 1) {
        lsum += __shfl_xor_sync(0xffffffffu, lsum, off);
        lsq  += __shfl_xor_sync(0xffffffffu, lsq, off);
    }
    if (lane == 0) { wred[wrp][0] = lsum; wred[wrp][1] = lsq; }
    __syncthreads();
    if (tid == 0) {
        float s0 = wred[0][0] + wred[1][0], q0 = wred[0][1] + wred[1][1];
        float s1 = wred[2][0] + wred[3][0], q1 = wred[2][1] + wred[3][1];
        g_part[((b * 2 + blockIdx.y) * 64 + blockIdx.x) * 2 + 0] = make_float2(s0, q0);
        g_part[((b * 2 + blockIdx.y) * 64 + blockIdx.x) * 2 + 1] = make_float2(s1, q1);
    }

    // coalesced write of y tile
    const int mrow = tid >> 1, seg = tid & 1;
    float* dst = &g_y[(long)(b * 128 + m0 + mrow) * 4096 + n0 + seg * 32];
    const float* src = &Osf[mrow * 68 + seg * 32];
#pragma unroll
    for (int j = 0; j < 8; j++)
        *(float4*)&dst[j * 4] = *(const float4*)&src[j * 4];
}

// ===========================================================================
// Kernel 3b: reduce GN partials. grid (4,4), 64 threads.
// ===========================================================================
__global__ void stats_kernel() {
    const int gg = blockIdx.x, b = blockIdx.y;
    const int by = gg >> 1, gl = gg & 1;
    const int t = threadIdx.x;
    float2 pv = g_part[((b * 2 + by) * 64 + t) * 2 + gl];
    float s = pv.x, ss = pv.y;
#pragma unroll
    for (int off = 16; off > 0; off >>= 1) {
        s  += __shfl_xor_sync(0xffffffffu, s, off);
        ss += __shfl_xor_sync(0xffffffffu, ss, off);
    }
    __shared__ float2 w2[2];
    if ((t & 31) == 0) w2[t >> 5] = make_float2(s, ss);
    __syncthreads();
    if (t == 0) {
        s = w2[0].x + w2[1].x;
        ss = w2[0].y + w2[1].y;
        const float invn = 1.f / 131072.f;
        float mean = s * invn;
        float var = ss * invn - mean * mean;
        g_stats[b * 4 + gg] = make_float2(mean, rsqrtf(var + GN_EPS));
    }
}

// ===========================================================================
// Kernel 4: GroupNorm affine + residual.
// ===========================================================================
__global__ __launch_bounds__(256) void norm_kernel(const float* __restrict__ x,
                                                   const float* __restrict__ gamma,
                                                   const float* __restrict__ beta,
                                                   float* __restrict__ out) {
    const int i4 = blockIdx.x * 256 + threadIdx.x;
    const int e = i4 * 4;
    const int c = (e >> 12) & 127;
    const int b = e >> 19;
    float2 st = g_stats[b * 4 + (c >> 5)];
    float ga = gamma[c] * st.y;
    float be = beta[c] - st.x * ga;
    float4 yv = *(const float4*)&g_y[e];
    float4 xv = *(const float4*)&x[e];
    float4 r;
    r.x = fmaf(yv.x, ga, be) + xv.x;
    r.y = fmaf(yv.y, ga, be) + xv.y;
    r.z = fmaf(yv.z, ga, be) + xv.z;
    r.w = fmaf(yv.w, ga, be) + xv.w;
    *(float4*)&out[e] = r;
}

// ===========================================================================
extern "C" void kernel_launch(void* const* d_in, const int* in_sizes, int n_in,
                              void* d_out, int out_size) {
    const float* x      = (const float*)d_in[0];
    const float* w_qkv  = (const float*)d_in[1];
    const float* w_out  = (const float*)d_in[2];
    const float* b_out  = (const float*)d_in[3];
    const float* gammap = (const float*)d_in[4];
    const float* betap  = (const float*)d_in[5];
    float* out = (float*)d_out;

    cvt_kernel<<<2048, 256>>>(x);
    qkv_kernel<<<dim3(64, 6, 4), 128>>>(w_qkv);
    attn_kernel<<<dim3(64, 4, 4), 128>>>();
    proj_kernel<<<dim3(64, 2, 4), 128>>>(w_out, b_out);
    stats_kernel<<<dim3(4, 4), 64>>>();
    norm_kernel<<<2048, 256>>>(x, gammap, betap, out);
}

// round 13
// speedup vs baseline: 1.0024x; 1.0024x over previous
#include <cuda_runtime.h>
#include <cuda_fp16.h>

typedef unsigned int u32;

#define GN_EPS 1e-5f
// (1/sqrt(32)) * log2(e): softmax runs in base-2 domain
#define QSCALE 0.25501817097393111f

// ---------------- scratch (static device allocations, allowed) -------------
__device__ __align__(16) __half g_xh[4 * 128 * 4096];    // x in fp16 [b][c][n]
__device__ __align__(16) __half g_qh[4 * 4 * 4096 * 32]; // [b][h][n][d]
__device__ __align__(16) __half g_kh[4 * 4 * 4096 * 32];
__device__ __align__(16) __half g_vh[4 * 4 * 4096 * 32];
__device__ __align__(16) __half g_aoh[4 * 128 * 4096];   // attn out fp16 [b][c][n]
__device__ __align__(16) float g_y[4 * 128 * 4096];      // proj out fp32 [b][c][n]
__device__ float2 g_part[4 * 2 * 64 * 2];
__device__ float2 g_stats[16];

// ---------------- PTX helpers ----------------------------------------------
__device__ __forceinline__ float ex2(float x) {
    float r; asm("ex2.approx.ftz.f32 %0, %1;" : "=f"(r) : "f"(x)); return r;
}
__device__ __forceinline__ u32 ex2h2(u32 x) {
    u32 r; asm("ex2.approx.f16x2 %0, %1;" : "=r"(r) : "r"(x)); return r;
}
__device__ __forceinline__ void ldsm_x4(u32* r, u32 addr) {
    asm volatile("ldmatrix.sync.aligned.m8n8.x4.shared.b16 {%0,%1,%2,%3}, [%4];"
                 : "=r"(r[0]), "=r"(r[1]), "=r"(r[2]), "=r"(r[3]) : "r"(addr));
}
__device__ __forceinline__ void ldsm_x4_t(u32* r, u32 addr) {
    asm volatile("ldmatrix.sync.aligned.m8n8.x4.trans.shared.b16 {%0,%1,%2,%3}, [%4];"
                 : "=r"(r[0]), "=r"(r[1]), "=r"(r[2]), "=r"(r[3]) : "r"(addr));
}
__device__ __forceinline__ void mma16816(float* c, const u32* a, const u32* b) {
    asm volatile("mma.sync.aligned.m16n8k16.row.col.f32.f16.f16.f32 "
                 "{%0,%1,%2,%3}, {%4,%5,%6,%7}, {%8,%9}, {%0,%1,%2,%3};"
                 : "+f"(c[0]), "+f"(c[1]), "+f"(c[2]), "+f"(c[3])
                 : "r"(a[0]), "r"(a[1]), "r"(a[2]), "r"(a[3]), "r"(b[0]), "r"(b[1]));
}
__device__ __forceinline__ u32 packh2(float a, float b) {
    __half2 h = __floats2half2_rn(a, b);
    return *(u32*)&h;
}
__device__ __forceinline__ __half2 u2h(u32 x) { __half2 h; *(u32*)&h = x; return h; }
__device__ __forceinline__ void cp16(u32 smem, const void* gmem) {
    asm volatile("cp.async.cg.shared.global [%0], [%1], 16;" :: "r"(smem), "l"(gmem));
}

// ===========================================================================
// Kernel 0: convert x fp32 -> fp16
// ===========================================================================
__global__ __launch_bounds__(256) void cvt_kernel(const float* __restrict__ x) {
    const int i = blockIdx.x * 256 + threadIdx.x;  // 524288 float4s
    float4 v = *(const float4*)&x[i * 4];
    *(__half2*)&g_xh[i * 4 + 0] = __floats2half2_rn(v.x, v.y);
    *(__half2*)&g_xh[i * 4 + 2] = __floats2half2_rn(v.z, v.w);
}

// ===========================================================================
// Kernel 1: QKV projection on tensor cores.
// out[m,n] = sum_k W[m,k] * x[k,n].  Tile 64(m) x 64(n), k=128.
// grid (64, 6, 4), 128 threads (4 warps, 16 m-rows each).
// ===========================================================================
__global__ __launch_bounds__(128) void qkv_kernel(const float* __restrict__ w) {
    __shared__ __align__(16) char smemBuf[17408 + 18432];
    __half* Ws = (__half*)smemBuf;                 // [64][136]
    __half* Xs = (__half*)(smemBuf + 17408);       // [128][72]
    __half* Osh = (__half*)smemBuf;                // overlay after mainloop [64n][72]

    const int b = blockIdx.z;
    const int n0 = blockIdx.x * 64;
    const int m0 = blockIdx.y * 64;
    const int tid = threadIdx.x;
    const int wrp = tid >> 5, lane = tid & 31;

    // stage W (fp32 -> fp16), 64x128
    for (int idx = tid; idx < 64 * 32; idx += 128) {
        int row = idx >> 5, c4 = idx & 31;
        float4 wv = *(const float4*)&w[(m0 + row) * 128 + c4 * 4];
        *(__half2*)&Ws[row * 136 + c4 * 4 + 0] = __floats2half2_rn(wv.x, wv.y);
        *(__half2*)&Ws[row * 136 + c4 * 4 + 2] = __floats2half2_rn(wv.z, wv.w);
    }
    // stage X tile [k=128][n=64] fp16
    for (int idx = tid; idx < 128 * 8; idx += 128) {
        int row = idx >> 3, seg = idx & 7;
        *(uint4*)&Xs[row * 72 + seg * 8] =
            *(const uint4*)&g_xh[(b * 128 + row) * 4096 + n0 + seg * 8];
    }
    __syncthreads();

    float acc[8][4];
#pragma unroll
    for (int i = 0; i < 8; i++)
#pragma unroll
        for (int j = 0; j < 4; j++) acc[i][j] = 0.f;

    const u32 wsAddr = (u32)__cvta_generic_to_shared(
        &Ws[(wrp * 16 + (lane & 15)) * 136 + (lane >> 4) * 8]);
    const int vm = lane >> 3;
    const u32 xsAddr = (u32)__cvta_generic_to_shared(
        &Xs[((vm & 1) * 8 + (lane & 7)) * 72 + (vm >> 1) * 8]);

#pragma unroll
    for (int kk = 0; kk < 8; kk++) {
        u32 wa[4];
        ldsm_x4(wa, wsAddr + kk * 32);
#pragma unroll
        for (int np = 0; np < 4; np++) {
            u32 xb[4];
            ldsm_x4_t(xb, xsAddr + kk * 16 * 144 + np * 32);
            mma16816(acc[2 * np + 0], wa, xb + 0);
            mma16816(acc[2 * np + 1], wa, xb + 2);
        }
    }
    __syncthreads();   // done with Ws/Xs, reuse as Osh

    const float sc = (m0 < 128) ? QSCALE : 1.0f;
    const int g = lane >> 2, t4 = lane & 3;
#pragma unroll
    for (int nt = 0; nt < 8; nt++) {
        int col = nt * 8 + 2 * t4;
        int r0 = wrp * 16 + g;
        Osh[(col + 0) * 72 + r0 + 0] = __float2half(acc[nt][0] * sc);
        Osh[(col + 1) * 72 + r0 + 0] = __float2half(acc[nt][1] * sc);
        Osh[(col + 0) * 72 + r0 + 8] = __float2half(acc[nt][2] * sc);
        Osh[(col + 1) * 72 + r0 + 8] = __float2half(acc[nt][3] * sc);
    }
    __syncthreads();

    const int which = m0 >> 7;
    __half* dstbase = (which == 0) ? g_qh : ((which == 1) ? g_kh : g_vh);
    const int h0 = (m0 >> 5) & 3;
    const int n = tid >> 1, hi = tid & 1;
    __half* dst = &dstbase[((long)(b * 4 + h0 + hi) * 4096 + n0 + n) * 32];
    const __half* src = &Osh[n * 72 + hi * 32];
    *(uint4*)&dst[0]  = *(const uint4*)&src[0];
    *(uint4*)&dst[8]  = *(const uint4*)&src[8];
    *(uint4*)&dst[16] = *(const uint4*)&src[16];
    *(uint4*)&dst[24] = *(const uint4*)&src[24];
}

// ===========================================================================
// Kernel 2: fp16 tensor-core flash attention, cp.async double-buffered KV,
// f16x2 exp2.  grid (64, 4, 4), 128 threads.
// ===========================================================================
__global__ __launch_bounds__(128) void attn_kernel() {
    __shared__ __align__(16) __half Qs[64 * 40];
    __shared__ __align__(16) __half Ks[2][64 * 40];
    __shared__ __align__(16) __half Vs[2][64 * 40];
    __shared__ __align__(16) float Os[64 * 33];

    const int b = blockIdx.z, hh = blockIdx.y;
    const int q0 = blockIdx.x * 64;
    const int tid = threadIdx.x;
    const int wrp = tid >> 5, lane = tid & 31;
    const long bh = (long)(b * 4 + hh) * 4096;

    // stage Q tile
    {
        const uint4* qg = (const uint4*)&g_qh[(bh + q0) * 32];
        for (int i = tid; i < 256; i += 128) {
            int row = i >> 2, ch = i & 3;
            *(uint4*)&Qs[row * 40 + ch * 8] = qg[i];
        }
    }

    const uint4* kg = (const uint4*)&g_kh[bh * 32];
    const uint4* vg = (const uint4*)&g_vh[bh * 32];
    const u32 ksmem = (u32)__cvta_generic_to_shared(&Ks[0][0]);
    const u32 vsmem = (u32)__cvta_generic_to_shared(&Vs[0][0]);
    // per-thread cp.async slots: i = tid (rows 0-31), i+128 (rows 32-63)
    const u32 off0 = (tid >> 2) * 80 + (tid & 3) * 16;
    const u32 off1 = off0 + 32 * 80;

    // prologue: issue tile 0 into buf 0
    cp16(ksmem + off0, kg + tid);
    cp16(ksmem + off1, kg + tid + 128);
    cp16(vsmem + off0, vg + tid);
    cp16(vsmem + off1, vg + tid + 128);
    asm volatile("cp.async.commit_group;");

    __syncthreads();
    // Q A-fragments (held all kernel)
    u32 qa[8];
    {
        int r = lane & 15, cc = lane >> 4;
        u32 a = (u32)__cvta_generic_to_shared(&Qs[(wrp * 16 + r) * 40 + cc * 8]);
        ldsm_x4(qa + 0, a);
        ldsm_x4(qa + 4, a + 32);
    }

    float o[4][4];
#pragma unroll
    for (int i = 0; i < 4; i++)
#pragma unroll
        for (int j = 0; j < 4; j++) o[i][j] = 0.f;
    float m0 = -1e30f, m1 = -1e30f, l0 = 0.f, l1 = 0.f;

    const u32 kaddr = (u32)__cvta_generic_to_shared(
        &Ks[0][(lane & 7) * 40 + (lane >> 3) * 8]);
    const int vm = lane >> 3;
    const u32 vaddr = (u32)__cvta_generic_to_shared(
        &Vs[0][((vm & 1) * 8 + (lane & 7)) * 40 + (vm >> 1) * 8]);

    for (int t0 = 0; t0 < 4096; t0 += 64) {
        const int buf = (t0 >> 6) & 1;
        const u32 bo = buf * 5120;
        // prefetch next tile into other buffer
        if (t0 + 64 < 4096) {
            const uint4* ks = kg + (t0 + 64) * 4;
            const uint4* vs = vg + (t0 + 64) * 4;
            const u32 nb = (buf ^ 1) * 5120;
            cp16(ksmem + nb + off0, ks + tid);
            cp16(ksmem + nb + off1, ks + tid + 128);
            cp16(vsmem + nb + off0, vs + tid);
            cp16(vsmem + nb + off1, vs + tid + 128);
        }
        asm volatile("cp.async.commit_group;");
        asm volatile("cp.async.wait_group 1;");
        __syncthreads();

        // ---- S = Q K^T
        float s[8][4];
#pragma unroll
        for (int nt = 0; nt < 8; nt++) {
            s[nt][0] = s[nt][1] = s[nt][2] = s[nt][3] = 0.f;
            u32 kb[4];
            ldsm_x4(kb, kaddr + bo + nt * 640);
            mma16816(s[nt], qa + 0, kb + 0);
            mma16816(s[nt], qa + 4, kb + 2);
        }

        // ---- online softmax (base-2, f16x2 exp)
        float mx0 = -1e30f, mx1 = -1e30f;
#pragma unroll
        for (int nt = 0; nt < 8; nt++) {
            mx0 = fmaxf(mx0, fmaxf(s[nt][0], s[nt][1]));
            mx1 = fmaxf(mx1, fmaxf(s[nt][2], s[nt][3]));
        }
        mx0 = fmaxf(mx0, __shfl_xor_sync(0xffffffffu, mx0, 1));
        mx0 = fmaxf(mx0, __shfl_xor_sync(0xffffffffu, mx0, 2));
        mx1 = fmaxf(mx1, __shfl_xor_sync(0xffffffffu, mx1, 1));
        mx1 = fmaxf(mx1, __shfl_xor_sync(0xffffffffu, mx1, 2));
        float nm0 = fmaxf(m0, mx0), nm1 = fmaxf(m1, mx1);
        float corr0 = ex2(m0 - nm0), corr1 = ex2(m1 - nm1);
        m0 = nm0; m1 = nm1;

        u32 pa[8][2];
#pragma unroll
        for (int nt = 0; nt < 8; nt++) {
            pa[nt][0] = ex2h2(packh2(s[nt][0] - m0, s[nt][1] - m0));
            pa[nt][1] = ex2h2(packh2(s[nt][2] - m1, s[nt][3] - m1));
        }
        // l-sums via shallow half2 tree then fp32
        __half2 t00 = __hadd2(__hadd2(u2h(pa[0][0]), u2h(pa[1][0])),
                              __hadd2(u2h(pa[2][0]), u2h(pa[3][0])));
        __half2 t01 = __hadd2(__hadd2(u2h(pa[4][0]), u2h(pa[5][0])),
                              __hadd2(u2h(pa[6][0]), u2h(pa[7][0])));
        __half2 t10 = __hadd2(__hadd2(u2h(pa[0][1]), u2h(pa[1][1])),
                              __hadd2(u2h(pa[2][1]), u2h(pa[3][1])));
        __half2 t11 = __hadd2(__hadd2(u2h(pa[4][1]), u2h(pa[5][1])),
                              __hadd2(u2h(pa[6][1]), u2h(pa[7][1])));
        float2 f0 = __half22float2(__hadd2(t00, t01));
        float2 f1 = __half22float2(__hadd2(t10, t11));
        l0 = l0 * corr0 + f0.x + f0.y;
        l1 = l1 * corr1 + f1.x + f1.y;
#pragma unroll
        for (int nd = 0; nd < 4; nd++) {
            o[nd][0] *= corr0; o[nd][1] *= corr0;
            o[nd][2] *= corr1; o[nd][3] *= corr1;
        }

        // ---- O += P V
#pragma unroll
        for (int kv = 0; kv < 4; kv++) {
            u32 A[4] = {pa[2 * kv][0], pa[2 * kv][1],
                        pa[2 * kv + 1][0], pa[2 * kv + 1][1]};
#pragma unroll
            for (int dh = 0; dh < 2; dh++) {
                u32 vb[4];
                ldsm_x4_t(vb, vaddr + bo + kv * 1280 + dh * 32);
                mma16816(o[2 * dh + 0], A, vb + 0);
                mma16816(o[2 * dh + 1], A, vb + 2);
            }
        }
        __syncthreads();
    }

    // ---- epilogue
    l0 += __shfl_xor_sync(0xffffffffu, l0, 1);
    l0 += __shfl_xor_sync(0xffffffffu, l0, 2);
    l1 += __shfl_xor_sync(0xffffffffu, l1, 1);
    l1 += __shfl_xor_sync(0xffffffffu, l1, 2);
    const float inv0 = 1.f / l0, inv1 = 1.f / l1;
    const int grp = lane >> 2, t4 = lane & 3;
#pragma unroll
    for (int nd = 0; nd < 4; nd++) {
        Os[(wrp * 16 + grp) * 33 + nd * 8 + 2 * t4 + 0] = o[nd][0] * inv0;
        Os[(wrp * 16 + grp) * 33 + nd * 8 + 2 * t4 + 1] = o[nd][1] * inv0;
        Os[(wrp * 16 + grp + 8) * 33 + nd * 8 + 2 * t4 + 0] = o[nd][2] * inv1;
        Os[(wrp * 16 + grp + 8) * 33 + nd * 8 + 2 * t4 + 1] = o[nd][3] * inv1;
    }
    __syncthreads();

    __half* ob = &g_aoh[(long)(b * 128 + hh * 32) * 4096 + q0];
    const int dd = tid >> 2, seg = tid & 3;
    union { __half hx[16]; uint4 ux[2]; } tmp;
#pragma unroll
    for (int i = 0; i < 16; i++)
        tmp.hx[i] = __float2half(Os[(seg * 16 + i) * 33 + dd]);
    uint4* dsth = (uint4*)&ob[dd * 4096 + seg * 16];
    dsth[0] = tmp.ux[0];
    dsth[1] = tmp.ux[1];
}

// ===========================================================================
// Kernel 3: output projection on tensor cores + bias + GN partials.
// grid (64, 2, 4), 128 threads.
// ===========================================================================
__global__ __launch_bounds__(128) void proj_kernel(const float* __restrict__ w,
                                                   const float* __restrict__ bias) {
    __shared__ __align__(16) char smemBuf[17408 + 18432];
    __half* Ws = (__half*)smemBuf;              // [64][136]
    __half* Xs = (__half*)(smemBuf + 17408);    // [128][72]
    float* Osf = (float*)smemBuf;               // overlay [64m][68]
    __shared__ float wred[4][2];

    const int b = blockIdx.z;
    const int n0 = blockIdx.x * 64;
    const int m0 = blockIdx.y * 64;
    const int tid = threadIdx.x;
    const int wrp = tid >> 5, lane = tid & 31;

    for (int idx = tid; idx < 64 * 32; idx += 128) {
        int row = idx >> 5, c4 = idx & 31;
        float4 wv = *(const float4*)&w[(m0 + row) * 128 + c4 * 4];
        *(__half2*)&Ws[row * 136 + c4 * 4 + 0] = __floats2half2_rn(wv.x, wv.y);
        *(__half2*)&Ws[row * 136 + c4 * 4 + 2] = __floats2half2_rn(wv.z, wv.w);
    }
    for (int idx = tid; idx < 128 * 8; idx += 128) {
        int row = idx >> 3, seg = idx & 7;
        *(uint4*)&Xs[row * 72 + seg * 8] =
            *(const uint4*)&g_aoh[(long)(b * 128 + row) * 4096 + n0 + seg * 8];
    }
    __syncthreads();

    float acc[8][4];
#pragma unroll
    for (int i = 0; i < 8; i++)
#pragma unroll
        for (int j = 0; j < 4; j++) acc[i][j] = 0.f;

    const u32 wsAddr = (u32)__cvta_generic_to_shared(
        &Ws[(wrp * 16 + (lane & 15)) * 136 + (lane >> 4) * 8]);
    const int vm = lane >> 3;
    const u32 xsAddr = (u32)__cvta_generic_to_shared(
        &Xs[((vm & 1) * 8 + (lane & 7)) * 72 + (vm >> 1) * 8]);

#pragma unroll
    for (int kk = 0; kk < 8; kk++) {
        u32 wa[4];
        ldsm_x4(wa, wsAddr + kk * 32);
#pragma unroll
        for (int np = 0; np < 4; np++) {
            u32 xb[4];
            ldsm_x4_t(xb, xsAddr + kk * 16 * 144 + np * 32);
            mma16816(acc[2 * np + 0], wa, xb + 0);
            mma16816(acc[2 * np + 1], wa, xb + 2);
        }
    }
    __syncthreads();   // reuse smem as Osf

    const int g = lane >> 2, t4 = lane & 3;
    const int r0 = wrp * 16 + g;
    const float b0 = bias[m0 + r0], b1 = bias[m0 + r0 + 8];
    float lsum = 0.f, lsq = 0.f;
#pragma unroll
    for (int nt = 0; nt < 8; nt++) {
        int col = nt * 8 + 2 * t4;
        float v0 = acc[nt][0] + b0, v1 = acc[nt][1] + b0;
        float v2 = acc[nt][2] + b1, v3 = acc[nt][3] + b1;
        Osf[(r0 + 0) * 68 + col + 0] = v0;
        Osf[(r0 + 0) * 68 + col + 1] = v1;
        Osf[(r0 + 8) * 68 + col + 0] = v2;
        Osf[(r0 + 8) * 68 + col + 1] = v3;
        lsum += (v0 + v1) + (v2 + v3);
        lsq = fmaf(v0, v0, lsq); lsq = fmaf(v1, v1, lsq);
        lsq = fmaf(v2, v2, lsq); lsq = fmaf(v3, v3, lsq);
    }
#pragma unroll
    for (int off = 16; off > 0; off >>= 1) {
        lsum += __shfl_xor_sync(0xffffffffu, lsum, off);
        lsq  += __shfl_xor_sync(0xffffffffu, lsq, off);
    }
    if (lane == 0) { wred[wrp][0] = lsum; wred[wrp][1] = lsq; }
    __syncthreads();
    if (tid == 0) {
        float s0 = wred[0][0] + wred[1][0], q0 = wred[0][1] + wred[1][1];
        float s1 = wred[2][0] + wred[3][0], q1 = wred[2][1] + wred[3][1];
        g_part[((b * 2 + blockIdx.y) * 64 + blockIdx.x) * 2 + 0] = make_float2(s0, q0);
        g_part[((b * 2 + blockIdx.y) * 64 + blockIdx.x) * 2 + 1] = make_float2(s1, q1);
    }

    // coalesced write of y tile
    const int mrow = tid >> 1, seg = tid & 1;
    float* dst = &g_y[(long)(b * 128 + m0 + mrow) * 4096 + n0 + seg * 32];
    const float* src = &Osf[mrow * 68 + seg * 32];
#pragma unroll
    for (int j = 0; j < 8; j++)
        *(float4*)&dst[j * 4] = *(const float4*)&src[j * 4];
}

// ===========================================================================
// Kernel 3b: reduce GN partials. grid (4,4), 64 threads.
// ===========================================================================
__global__ void stats_kernel() {
    const int gg = blockIdx.x, b = blockIdx.y;
    const int by = gg >> 1, gl = gg & 1;
    const int t = threadIdx.x;
    float2 pv = g_part[((b * 2 + by) * 64 + t) * 2 + gl];
    float s = pv.x, ss = pv.y;
#pragma unroll
    for (int off = 16; off > 0; off >>= 1) {
        s  += __shfl_xor_sync(0xffffffffu, s, off);
        ss += __shfl_xor_sync(0xffffffffu, ss, off);
    }
    __shared__ float2 w2[2];
    if ((t & 31) == 0) w2[t >> 5] = make_float2(s, ss);
    __syncthreads();
    if (t == 0) {
        s = w2[0].x + w2[1].x;
        ss = w2[0].y + w2[1].y;
        const float invn = 1.f / 131072.f;
        float mean = s * invn;
        float var = ss * invn - mean * mean;
        g_stats[b * 4 + gg] = make_float2(mean, rsqrtf(var + GN_EPS));
    }
}

// ===========================================================================
// Kernel 4: GroupNorm affine + residual.
// ===========================================================================
__global__ __launch_bounds__(256) void norm_kernel(const float* __restrict__ x,
                                                   const float* __restrict__ gamma,
                                                   const float* __restrict__ beta,
                                                   float* __restrict__ out) {
    const int i4 = blockIdx.x * 256 + threadIdx.x;
    const int e = i4 * 4;
    const int c = (e >> 12) & 127;
    const int b = e >> 19;
    float2 st = g_stats[b * 4 + (c >> 5)];
    float ga = gamma[c] * st.y;
    float be = beta[c] - st.x * ga;
    float4 yv = *(const float4*)&g_y[e];
    float4 xv = *(const float4*)&x[e];
    float4 r;
    r.x = fmaf(yv.x, ga, be) + xv.x;
    r.y = fmaf(yv.y, ga, be) + xv.y;
    r.z = fmaf(yv.z, ga, be) + xv.z;
    r.w = fmaf(yv.w, ga, be) + xv.w;
    *(float4*)&out[e] = r;
}

// ===========================================================================
extern "C" void kernel_launch(void* const* d_in, const int* in_sizes, int n_in,
                              void* d_out, int out_size) {
    const float* x      = (const float*)d_in[0];
    const float* w_qkv  = (const float*)d_in[1];
    const float* w_out  = (const float*)d_in[2];
    const float* b_out  = (const float*)d_in[3];
    const float* gammap = (const float*)d_in[4];
    const float* betap  = (const float*)d_in[5];
    float* out = (float*)d_out;

    cvt_kernel<<<2048, 256>>>(x);
    qkv_kernel<<<dim3(64, 6, 4), 128>>>(w_qkv);
    attn_kernel<<<dim3(64, 4, 4), 128>>>();
    proj_kernel<<<dim3(64, 2, 4), 128>>>(w_out, b_out);
    stats_kernel<<<dim3(4, 4), 64>>>();
    norm_kernel<<<2048, 256>>>(x, gammap, betap, out);
}